// round 2
// baseline (speedup 1.0000x reference)
#include <cuda_runtime.h>

#define BETA  0.95f
#define PI_F  3.141592653589793f
#define BB    32
#define NN    1024

// Scratch (no device allocation allowed)
__device__ float g_spk0[BB * NN];
__device__ float g_mean[2 * BB];
__device__ float g_loss[2];

// ---------------------------------------------------------------------------
// prep: row means of prev_spk0 (rows 0..31) and prev_spk1 (rows 32..63),
// and zero the loss accumulators.
// ---------------------------------------------------------------------------
__global__ void prep_kernel(const float* __restrict__ p0,
                            const float* __restrict__ p1) {
    int r = blockIdx.x;                 // 0..63
    const float* row = (r < BB) ? (p0 + (size_t)r * NN)
                                : (p1 + (size_t)(r - BB) * NN);
    int tid = threadIdx.x;              // 256 threads
    float s = 0.f;
    for (int k = tid; k < NN; k += 256) s += row[k];
    __shared__ float sm[8];
    #pragma unroll
    for (int o = 16; o; o >>= 1) s += __shfl_down_sync(0xffffffffu, s, o);
    if ((tid & 31) == 0) sm[tid >> 5] = s;
    __syncthreads();
    if (tid == 0) {
        float t = 0.f;
        #pragma unroll
        for (int i = 0; i < 8; i++) t += sm[i];
        g_mean[r] = t * (1.0f / NN);
    }
    if (r == 0 && tid < 2) g_loss[tid] = 0.f;
}

// ---------------------------------------------------------------------------
// Fused layer kernel:
//   cur = x @ W^T ; mem = beta*mem + cur ; spk = mem>1 ; mem -= spk
//   a   = bf * prev * surrogate(mem-1)
//   trace = beta*itr + x
//   dW[b,h,j] = a[b,h] * trace[b,j]   (written directly, coalesced float2)
//   loss partial: sum spk*(prev - mean[b])  -> atomicAdd
// grid: (8 h-tiles, 32 batch), 128 threads
// ---------------------------------------------------------------------------
__global__ void layer_kernel(const float* __restrict__ x,
                             const float* __restrict__ W,
                             const float* __restrict__ mem_in,
                             const float* __restrict__ prev,
                             const float* __restrict__ itr,
                             const float* __restrict__ mean,     // per-b (32)
                             const int*   __restrict__ bf_ptr,
                             float* __restrict__ mem_out,
                             float* __restrict__ spk_out,
                             float* __restrict__ dW_out,         // 8B-aligned
                             float* __restrict__ loss_slot) {
    __shared__ __align__(16) float xs[NN];
    __shared__ __align__(16) float ts[NN];
    __shared__ float as_[128];

    const int b   = blockIdx.y;
    const int tid = threadIdx.x;

    const float* xrow = x   + (size_t)b * NN;
    const float* trow = itr + (size_t)b * NN;
    for (int k = tid; k < NN; k += 128) {
        float xv = xrow[k];
        xs[k] = xv;
        ts[k] = BETA * trow[k] + xv;
    }
    __syncthreads();

    const int h = blockIdx.x * 128 + tid;
    const float4* wr = (const float4*)(W + (size_t)h * NN);
    float a0 = 0.f, a1 = 0.f, a2 = 0.f, a3 = 0.f;
    #pragma unroll 8
    for (int i = 0; i < NN / 4; i++) {
        float4 w  = wr[i];
        float4 xv = *(const float4*)&xs[4 * i];
        a0 += w.x * xv.x;
        a1 += w.y * xv.y;
        a2 += w.z * xv.z;
        a3 += w.w * xv.w;
    }
    float dot = (a0 + a1) + (a2 + a3);

    const int idx = b * NN + h;
    float m = BETA * mem_in[idx] + dot;
    float s = (m > 1.0f) ? 1.0f : 0.0f;
    m -= s;
    mem_out[idx] = m;
    spk_out[idx] = s;

    const float bfv = (float)(*bf_ptr);
    float pv  = prev[idx];
    float u   = PI_F * (m - 1.0f);
    float sur = 1.0f / (PI_F * (1.0f + u * u));
    as_[tid]  = bfv * pv * sur;

    // loss partial: sum over h of spk * (prev - mean[b])
    float c = s * (pv - mean[b]);
    #pragma unroll
    for (int o = 16; o; o >>= 1) c += __shfl_down_sync(0xffffffffu, c, o);
    if ((tid & 31) == 0) atomicAdd(loss_slot, c);
    __syncthreads();

    // Cooperative, coalesced tile store: 128 rows x 1024 cols = 65536 float2
    float* dst = dW_out + (size_t)b * (NN * (size_t)NN)
                        + (size_t)blockIdx.x * 128 * NN;
    for (int f = tid; f < 128 * NN / 2; f += 128) {
        int i = f >> 9;            // f / 512
        int j = (f & 511) << 1;    // even column
        float a = as_[i];
        float2 v;
        v.x = a * ts[j];
        v.y = a * ts[j + 1];
        *(float2*)(dst + (size_t)i * NN + j) = v;
    }
}

// ---------------------------------------------------------------------------
// finalize losses: mean over batch of -bf * (spk*fb).sum
// ---------------------------------------------------------------------------
__global__ void final_kernel(const int* __restrict__ bf_ptr,
                             float* __restrict__ losses) {
    if (threadIdx.x < 2)
        losses[threadIdx.x] = -((float)(*bf_ptr)) * g_loss[threadIdx.x]
                              * (1.0f / (float)BB);
}

extern "C" void kernel_launch(void* const* d_in, const int* in_sizes, int n_in,
                              void* d_out, int out_size) {
    (void)in_sizes; (void)n_in; (void)out_size;
    const float* inp  = (const float*)d_in[0];
    const float* W0   = (const float*)d_in[1];
    const float* W1   = (const float*)d_in[2];
    const float* mem0 = (const float*)d_in[3];
    const float* mem1 = (const float*)d_in[4];
    const float* ps0  = (const float*)d_in[5];
    const float* ps1  = (const float*)d_in[6];
    const float* it0  = (const float*)d_in[7];
    const float* it1  = (const float*)d_in[8];
    const int*   bf   = (const int*)d_in[9];   // low 32 bits of the scalar

    float* out    = (float*)d_out;
    float* spk1_o = out;                               // (32,1024)
    float* mem0_o = out + BB * NN;                     // (32,1024)
    float* mem1_o = out + 2 * BB * NN;                 // (32,1024)
    float* loss_o = out + 3 * BB * NN;                 // (2,)
    float* dW0_o  = out + 3 * BB * NN + 2;             // (32,1024,1024)
    float* dW1_o  = dW0_o + (size_t)BB * NN * NN;      // (32,1024,1024)

    float* spk0_s; cudaGetSymbolAddress((void**)&spk0_s, g_spk0);
    float* mean_s; cudaGetSymbolAddress((void**)&mean_s, g_mean);
    float* loss_s; cudaGetSymbolAddress((void**)&loss_s, g_loss);

    prep_kernel<<<64, 256>>>(ps0, ps1);

    dim3 grid(8, BB);
    layer_kernel<<<grid, 128>>>(inp, W0, mem0, ps0, it0, mean_s, bf,
                                mem0_o, spk0_s, dW0_o, loss_s + 0);
    layer_kernel<<<grid, 128>>>(spk0_s, W1, mem1, ps1, it1, mean_s + BB, bf,
                                mem1_o, spk1_o, dW1_o, loss_s + 1);

    final_kernel<<<1, 32>>>(bf, loss_o);
}

// round 4
// speedup vs baseline: 1.5644x; 1.5644x over previous
#include <cuda_runtime.h>

#define BETA  0.95f
#define PI_F  3.141592653589793f
#define BB    32
#define NN    1024

// Scratch (device globals — no allocation allowed)
__device__ float g_spk0[BB * NN];
__device__ float g_a[2 * BB * NN];      // bf * prev * surrogate(mem-1), per layer
__device__ float g_t[2 * BB * NN];      // trace = beta*itr + x, per layer
__device__ float g_part[2 * BB * 8];    // per-block loss partials

// ---------------------------------------------------------------------------
// Fused layer compute: cur = x@W^T ; LIF update ; a-coeffs ; trace ; loss part
// grid (8 h-tiles, 32 batch), 128 threads
// ---------------------------------------------------------------------------
__global__ void compute_kernel(const float* __restrict__ x,
                               const float* __restrict__ W,
                               const float* __restrict__ mem_in,
                               const float* __restrict__ prev,
                               const float* __restrict__ itr,
                               const int*   __restrict__ bf_ptr,
                               float* __restrict__ mem_out,
                               float* __restrict__ spk_out,
                               float* __restrict__ a_out,     // (32,1024)
                               float* __restrict__ t_out,     // (32,1024)
                               float* __restrict__ part_out)  // (32,8)
{
    __shared__ __align__(16) float xs[NN];
    __shared__ __align__(16) float ts[NN];
    __shared__ float redm[4];
    __shared__ float redc[4];

    const int b   = blockIdx.y;
    const int tid = threadIdx.x;
    const int wid = tid >> 5, lane = tid & 31;

    const float* xrow = x   + (size_t)b * NN;
    const float* trow = itr + (size_t)b * NN;
    const float* prow = prev + (size_t)b * NN;

    float pm = 0.f;
    for (int k = tid; k < NN; k += 128) {
        float xv = xrow[k];
        xs[k] = xv;
        ts[k] = BETA * trow[k] + xv;
        pm += prow[k];
    }
    // block reduce pm -> mean
    #pragma unroll
    for (int o = 16; o; o >>= 1) pm += __shfl_down_sync(0xffffffffu, pm, o);
    if (lane == 0) redm[wid] = pm;
    __syncthreads();
    const float mean = (redm[0] + redm[1] + redm[2] + redm[3]) * (1.0f / NN);

    const int h = blockIdx.x * 128 + tid;
    const float4* wr = (const float4*)(W + (size_t)h * NN);
    float a0 = 0.f, a1 = 0.f, a2 = 0.f, a3 = 0.f;
    #pragma unroll 8
    for (int i = 0; i < NN / 4; i++) {
        float4 w  = wr[i];
        float4 xv = *(const float4*)&xs[4 * i];
        a0 += w.x * xv.x;
        a1 += w.y * xv.y;
        a2 += w.z * xv.z;
        a3 += w.w * xv.w;
    }
    float dot = (a0 + a1) + (a2 + a3);

    const int idx = b * NN + h;
    float m = BETA * mem_in[idx] + dot;
    float s = (m > 1.0f) ? 1.0f : 0.0f;
    m -= s;
    mem_out[idx] = m;
    spk_out[idx] = s;

    const float bfv = (float)(*bf_ptr);
    float pv  = prow[h];
    float u   = PI_F * (m - 1.0f);
    float sur = 1.0f / (PI_F * (1.0f + u * u));
    a_out[idx] = bfv * pv * sur;

    // loss partial: sum over this block's 128 h of spk*(prev - mean)
    float c = s * (pv - mean);
    #pragma unroll
    for (int o = 16; o; o >>= 1) c += __shfl_down_sync(0xffffffffu, c, o);
    if (lane == 0) redc[wid] = c;

    // one block per b writes the trace row
    if (blockIdx.x == 0)
        for (int k = tid; k < NN; k += 128)
            t_out[b * NN + k] = ts[k];

    __syncthreads();
    if (tid == 0)
        part_out[b * 8 + blockIdx.x] = redc[0] + redc[1] + redc[2] + redc[3];
}

// ---------------------------------------------------------------------------
// Giant store kernel: writes BOTH dW0 and dW1 in one full-chip wave.
// grid 512 blocks (layer,b,itile), 512 threads. Each thread owns one column
// pair (tx,ty in regs) and walks 128 rows; a[i] via broadcast LDS.
// Streaming stores (evict-first) — dW is write-once data.
// ---------------------------------------------------------------------------
__global__ void store_kernel(const float* __restrict__ a_all,
                             const float* __restrict__ t_all,
                             float* __restrict__ dW0,
                             float* __restrict__ dW1)
{
    __shared__ float as_[128];
    const int bid   = blockIdx.x;
    const int layer = bid >> 8;
    const int rem   = bid & 255;
    const int b     = rem >> 3;
    const int itile = rem & 7;
    const int tid   = threadIdx.x;          // 0..511

    const float* a = a_all + layer * (BB * NN) + b * NN + itile * 128;
    const float* t = t_all + layer * (BB * NN) + b * NN;
    if (tid < 128) as_[tid] = a[tid];
    const float tx = t[2 * tid];
    const float ty = t[2 * tid + 1];
    __syncthreads();

    float* dst = (layer ? dW1 : dW0)
               + (size_t)b * NN * NN + (size_t)itile * 128 * NN + 2 * tid;
    #pragma unroll 4
    for (int i = 0; i < 128; i++) {
        float av = as_[i];
        float2 v;
        v.x = av * tx;
        v.y = av * ty;
        __stcs((float2*)(dst + (size_t)i * NN), v);
    }
}

// ---------------------------------------------------------------------------
// finalize losses: losses[l] = -bf * (sum of 256 partials) / 32
// ---------------------------------------------------------------------------
__global__ void final_kernel(const int* __restrict__ bf_ptr,
                             const float* __restrict__ part,
                             float* __restrict__ losses)
{
    __shared__ float red[8];
    const int l = blockIdx.x;
    const int tid = threadIdx.x;             // 256
    float s = part[l * 256 + tid];
    #pragma unroll
    for (int o = 16; o; o >>= 1) s += __shfl_down_sync(0xffffffffu, s, o);
    if ((tid & 31) == 0) red[tid >> 5] = s;
    __syncthreads();
    if (tid == 0) {
        float t = 0.f;
        #pragma unroll
        for (int i = 0; i < 8; i++) t += red[i];
        losses[l] = -((float)(*bf_ptr)) * t * (1.0f / (float)BB);
    }
}

extern "C" void kernel_launch(void* const* d_in, const int* in_sizes, int n_in,
                              void* d_out, int out_size) {
    (void)in_sizes; (void)n_in; (void)out_size;
    const float* inp  = (const float*)d_in[0];
    const float* W0   = (const float*)d_in[1];
    const float* W1   = (const float*)d_in[2];
    const float* mem0 = (const float*)d_in[3];
    const float* mem1 = (const float*)d_in[4];
    const float* ps0  = (const float*)d_in[5];
    const float* ps1  = (const float*)d_in[6];
    const float* it0  = (const float*)d_in[7];
    const float* it1  = (const float*)d_in[8];
    const int*   bf   = (const int*)d_in[9];

    float* out    = (float*)d_out;
    float* spk1_o = out;                               // (32,1024)
    float* mem0_o = out + BB * NN;                     // (32,1024)
    float* mem1_o = out + 2 * BB * NN;                 // (32,1024)
    float* loss_o = out + 3 * BB * NN;                 // (2,)
    float* dW0_o  = out + 3 * BB * NN + 2;             // (32,1024,1024)
    float* dW1_o  = dW0_o + (size_t)BB * NN * NN;      // (32,1024,1024)

    float* spk0_s; cudaGetSymbolAddress((void**)&spk0_s, g_spk0);
    float* a_s;    cudaGetSymbolAddress((void**)&a_s,    g_a);
    float* t_s;    cudaGetSymbolAddress((void**)&t_s,    g_t);
    float* part_s; cudaGetSymbolAddress((void**)&part_s, g_part);

    dim3 grid(8, BB);
    compute_kernel<<<grid, 128>>>(inp, W0, mem0, ps0, it0, bf,
                                  mem0_o, spk0_s, a_s, t_s, part_s);
    compute_kernel<<<grid, 128>>>(spk0_s, W1, mem1, ps1, it1, bf,
                                  mem1_o, spk1_o,
                                  a_s + BB * NN, t_s + BB * NN,
                                  part_s + BB * 8);

    store_kernel<<<512, 512>>>(a_s, t_s, dW0_o, dW1_o);

    final_kernel<<<2, 256>>>(bf, part_s, loss_o);
}

// round 5
// speedup vs baseline: 1.8768x; 1.1996x over previous
#include <cuda_runtime.h>

#define BETA  0.95f
#define PI_F  3.141592653589793f
#define BB    32
#define NN    1024
#define BG    4        // batches per compute block

// Scratch (device globals — no allocation allowed)
__device__ float g_spk0[BB * NN];
__device__ float g_a[2 * BB * NN];      // bf * prev * surrogate(mem-1)
__device__ float g_t[2 * BB * NN];      // trace = beta*itr + x
__device__ float g_part[2 * BB * 8];    // per-(b,htile) loss partials

// ---------------------------------------------------------------------------
// Fused layer compute, batch-blocked: each block = 128 h-rows x 4 batches.
// W row is loaded ONCE and used for 4 dots -> W L2 traffic 32MB/layer (was 128).
// grid (8 htiles, 8 bgroups), 128 threads
// ---------------------------------------------------------------------------
__global__ void compute_kernel(const float* __restrict__ x,
                               const float* __restrict__ W,
                               const float* __restrict__ mem_in,
                               const float* __restrict__ prev,
                               const float* __restrict__ itr,
                               const int*   __restrict__ bf_ptr,
                               float* __restrict__ mem_out,
                               float* __restrict__ spk_out,
                               float* __restrict__ a_out,     // (32,1024)
                               float* __restrict__ t_out,     // (32,1024)
                               float* __restrict__ part_out)  // (32,8)
{
    __shared__ __align__(16) float xs[BG][NN];
    __shared__ float redm[BG][4];
    __shared__ float redc[BG][4];

    const int tid  = threadIdx.x;
    const int wid  = tid >> 5, lane = tid & 31;
    const int b0   = blockIdx.y * BG;

    // load x rows to smem, compute prev-row sums, emit trace rows (htile 0 only)
    float pm[BG];
    #pragma unroll
    for (int bb = 0; bb < BG; bb++) {
        const float* xrow = x    + (size_t)(b0 + bb) * NN;
        const float* prow = prev + (size_t)(b0 + bb) * NN;
        const float* trow = itr  + (size_t)(b0 + bb) * NN;
        float s = 0.f;
        for (int k = tid; k < NN; k += 128) {
            float v = xrow[k];
            xs[bb][k] = v;
            s += prow[k];
            if (blockIdx.x == 0)
                t_out[(size_t)(b0 + bb) * NN + k] = BETA * trow[k] + v;
        }
        pm[bb] = s;
    }
    #pragma unroll
    for (int bb = 0; bb < BG; bb++) {
        float s = pm[bb];
        #pragma unroll
        for (int o = 16; o; o >>= 1) s += __shfl_down_sync(0xffffffffu, s, o);
        if (lane == 0) redm[bb][wid] = s;
    }
    __syncthreads();

    float mean[BG];
    #pragma unroll
    for (int bb = 0; bb < BG; bb++)
        mean[bb] = (redm[bb][0] + redm[bb][1] + redm[bb][2] + redm[bb][3])
                   * (1.0f / NN);

    // 4 dots per thread, one W-row pass
    const int h = blockIdx.x * 128 + tid;
    const float4* wr = (const float4*)(W + (size_t)h * NN);
    float accA[BG], accB[BG];
    #pragma unroll
    for (int bb = 0; bb < BG; bb++) { accA[bb] = 0.f; accB[bb] = 0.f; }

    #pragma unroll 4
    for (int i = 0; i < NN / 4; i++) {
        float4 w = wr[i];
        #pragma unroll
        for (int bb = 0; bb < BG; bb++) {
            float4 xv = *(const float4*)&xs[bb][4 * i];
            accA[bb] = fmaf(w.x, xv.x, accA[bb]);
            accB[bb] = fmaf(w.y, xv.y, accB[bb]);
            accA[bb] = fmaf(w.z, xv.z, accA[bb]);
            accB[bb] = fmaf(w.w, xv.w, accB[bb]);
        }
    }

    const float bfv = (float)(*bf_ptr);
    #pragma unroll
    for (int bb = 0; bb < BG; bb++) {
        const int idx = (b0 + bb) * NN + h;
        float m = BETA * mem_in[idx] + (accA[bb] + accB[bb]);
        float s = (m > 1.0f) ? 1.0f : 0.0f;
        m -= s;
        mem_out[idx] = m;
        spk_out[idx] = s;

        float pv  = prev[idx];
        float u   = PI_F * (m - 1.0f);
        float sur = 1.0f / (PI_F * (1.0f + u * u));
        a_out[idx] = bfv * pv * sur;

        float c = s * (pv - mean[bb]);
        #pragma unroll
        for (int o = 16; o; o >>= 1) c += __shfl_down_sync(0xffffffffu, c, o);
        if (lane == 0) redc[bb][wid] = c;
    }
    __syncthreads();
    if (tid < BG)
        part_out[(b0 + tid) * 8 + blockIdx.x] =
            redc[tid][0] + redc[tid][1] + redc[tid][2] + redc[tid][3];
}

// ---------------------------------------------------------------------------
// Store kernel: dW[b,i,j] = a[b,i]*t[b,j], both layers, one full-chip wave.
// 2048 blocks x 128 threads (32-row tiles) -> 16 blocks/SM, all resident.
// Block 2048 computes the losses (hidden under the store wave).
// ---------------------------------------------------------------------------
__global__ void store_final_kernel(const float* __restrict__ a_all,
                                   const float* __restrict__ t_all,
                                   float* __restrict__ dW0,
                                   float* __restrict__ dW1,
                                   const float* __restrict__ part,
                                   const int*   __restrict__ bf_ptr,
                                   float* __restrict__ losses)
{
    const int bid = blockIdx.x;
    const int tid = threadIdx.x;          // 128

    if (bid == 2048) {                    // loss finalize
        if (tid < 2) {
            float s = 0.f;
            for (int i = 0; i < 256; i++) s += part[tid * 256 + i];
            losses[tid] = -((float)(*bf_ptr)) * s * (1.0f / (float)BB);
        }
        return;
    }

    __shared__ float as_[32];
    const int layer = bid >> 10;
    const int rem   = bid & 1023;
    const int b     = rem >> 5;
    const int tile  = rem & 31;           // 32-row tile

    const float*  a = a_all + layer * (BB * NN) + b * NN + tile * 32;
    const float2* t = (const float2*)(t_all + layer * (BB * NN) + b * NN);
    if (tid < 32) as_[tid] = a[tid];
    float2 tv[4];
    #pragma unroll
    for (int j = 0; j < 4; j++) tv[j] = t[tid + 128 * j];
    __syncthreads();

    float* dst = (layer ? dW1 : dW0)
               + (size_t)b * NN * NN + (size_t)tile * 32 * NN;
    #pragma unroll 4
    for (int i = 0; i < 32; i++) {
        float av = as_[i];
        float* row = dst + (size_t)i * NN;
        #pragma unroll
        for (int j = 0; j < 4; j++) {
            float2 v;
            v.x = av * tv[j].x;
            v.y = av * tv[j].y;
            __stcs((float2*)row + tid + 128 * j, v);
        }
    }
}

extern "C" void kernel_launch(void* const* d_in, const int* in_sizes, int n_in,
                              void* d_out, int out_size) {
    (void)in_sizes; (void)n_in; (void)out_size;
    const float* inp  = (const float*)d_in[0];
    const float* W0   = (const float*)d_in[1];
    const float* W1   = (const float*)d_in[2];
    const float* mem0 = (const float*)d_in[3];
    const float* mem1 = (const float*)d_in[4];
    const float* ps0  = (const float*)d_in[5];
    const float* ps1  = (const float*)d_in[6];
    const float* it0  = (const float*)d_in[7];
    const float* it1  = (const float*)d_in[8];
    const int*   bf   = (const int*)d_in[9];

    float* out    = (float*)d_out;
    float* spk1_o = out;                               // (32,1024)
    float* mem0_o = out + BB * NN;                     // (32,1024)
    float* mem1_o = out + 2 * BB * NN;                 // (32,1024)
    float* loss_o = out + 3 * BB * NN;                 // (2,)
    float* dW0_o  = out + 3 * BB * NN + 2;             // (32,1024,1024)
    float* dW1_o  = dW0_o + (size_t)BB * NN * NN;      // (32,1024,1024)

    float* spk0_s; cudaGetSymbolAddress((void**)&spk0_s, g_spk0);
    float* a_s;    cudaGetSymbolAddress((void**)&a_s,    g_a);
    float* t_s;    cudaGetSymbolAddress((void**)&t_s,    g_t);
    float* part_s; cudaGetSymbolAddress((void**)&part_s, g_part);

    dim3 cgrid(8, BB / BG);
    compute_kernel<<<cgrid, 128>>>(inp, W0, mem0, ps0, it0, bf,
                                   mem0_o, spk0_s, a_s, t_s, part_s);
    compute_kernel<<<cgrid, 128>>>(spk0_s, W1, mem1, ps1, it1, bf,
                                   mem1_o, spk1_o,
                                   a_s + BB * NN, t_s + BB * NN,
                                   part_s + BB * 8);

    store_final_kernel<<<2049, 128>>>(a_s, t_s, dW0_o, dW1_o,
                                      part_s, bf, loss_o);
}

// round 6
// speedup vs baseline: 2.4414x; 1.3008x over previous
#include <cuda_runtime.h>

#define BETA  0.95f
#define PI_F  3.141592653589793f
#define BB    32
#define NN    1024
#define BG    4        // batches per compute block

// Scratch (device globals — no allocation allowed)
__device__ float g_spk0[BB * NN];
__device__ float g_a[2 * BB * NN];        // bf * prev * surrogate(mem-1)
__device__ float g_t[2 * BB * NN];        // trace = beta*itr + x
__device__ float g_part[2 * BB * 128 * 2]; // per-(layer,b,htile) {spk*prev, spk}

// ---------------------------------------------------------------------------
// Layer compute, occupancy-first: one warp per h-row, lanes split K.
// Block: 8 warps = 8 h-rows x 4 batches. Grid (128 htiles, 8 bgroups) = 1024
// blocks -> ~55 warps/SM. W loads perfectly coalesced (512B/warp/iter).
// ---------------------------------------------------------------------------
__global__ void __launch_bounds__(256)
compute_kernel(const float* __restrict__ x,
               const float* __restrict__ W,
               const float* __restrict__ mem_in,
               const float* __restrict__ prev,
               const float* __restrict__ itr,
               const int*   __restrict__ bf_ptr,
               float* __restrict__ mem_out,
               float* __restrict__ spk_out,
               float* __restrict__ a_out,     // (32,1024)
               float* __restrict__ t_out,     // (32,1024)
               float* __restrict__ part)      // (32,128,2) for this layer
{
    __shared__ __align__(16) float xs[BG][NN];
    __shared__ float redc[8][BG][2];

    const int tid  = threadIdx.x;            // 256
    const int w    = tid >> 5, lane = tid & 31;
    const int ht   = blockIdx.x;             // 0..127
    const int b0   = blockIdx.y * BG;

    #pragma unroll
    for (int r = 0; r < BG; r++) {
        const float* xrow = x + (size_t)(b0 + r) * NN;
        for (int k = tid; k < NN; k += 256) xs[r][k] = xrow[k];
    }
    __syncthreads();

    // trace emit (htile 0 only)
    if (ht == 0) {
        #pragma unroll
        for (int r = 0; r < BG; r++) {
            const float* trow = itr + (size_t)(b0 + r) * NN;
            for (int k = tid; k < NN; k += 256)
                t_out[(size_t)(b0 + r) * NN + k] = BETA * trow[k] + xs[r][k];
        }
    }

    // dot products: warp w owns h-row, lanes split K (coalesced float4)
    const int h = ht * 8 + w;
    const float4* wr  = (const float4*)(W + (size_t)h * NN);
    const float4* x0p = (const float4*)xs[0];
    const float4* x1p = (const float4*)xs[1];
    const float4* x2p = (const float4*)xs[2];
    const float4* x3p = (const float4*)xs[3];
    float acc0 = 0.f, acc1 = 0.f, acc2 = 0.f, acc3 = 0.f;
    #pragma unroll
    for (int i = 0; i < 8; i++) {
        const int o = i * 32 + lane;
        float4 wv = wr[o];
        float4 v;
        v = x0p[o];
        acc0 = fmaf(wv.x, v.x, fmaf(wv.y, v.y, fmaf(wv.z, v.z, fmaf(wv.w, v.w, acc0))));
        v = x1p[o];
        acc1 = fmaf(wv.x, v.x, fmaf(wv.y, v.y, fmaf(wv.z, v.z, fmaf(wv.w, v.w, acc1))));
        v = x2p[o];
        acc2 = fmaf(wv.x, v.x, fmaf(wv.y, v.y, fmaf(wv.z, v.z, fmaf(wv.w, v.w, acc2))));
        v = x3p[o];
        acc3 = fmaf(wv.x, v.x, fmaf(wv.y, v.y, fmaf(wv.z, v.z, fmaf(wv.w, v.w, acc3))));
    }
    #pragma unroll
    for (int o = 16; o; o >>= 1) {
        acc0 += __shfl_xor_sync(0xffffffffu, acc0, o);
        acc1 += __shfl_xor_sync(0xffffffffu, acc1, o);
        acc2 += __shfl_xor_sync(0xffffffffu, acc2, o);
        acc3 += __shfl_xor_sync(0xffffffffu, acc3, o);
    }

    // epilogue: lanes 0..3 handle batch b0+lane
    if (lane < BG) {
        float dot = (lane == 0) ? acc0 : (lane == 1) ? acc1
                  : (lane == 2) ? acc2 : acc3;
        const int idx = (b0 + lane) * NN + h;
        float m = BETA * mem_in[idx] + dot;
        float s = (m > 1.0f) ? 1.0f : 0.0f;
        m -= s;
        mem_out[idx] = m;
        spk_out[idx] = s;

        float pv  = prev[idx];
        float u   = PI_F * (m - 1.0f);
        float sur = 1.0f / (PI_F * (1.0f + u * u));
        a_out[idx] = ((float)(*bf_ptr)) * pv * sur;

        redc[w][lane][0] = s * pv;   // spk*prev partial
        redc[w][lane][1] = s;        // spk partial
    }
    __syncthreads();

    // per-block loss partials: thread t<8 -> (bb=t>>1, comp=t&1), sum 8 warps
    if (tid < 2 * BG) {
        const int bb = tid >> 1, comp = tid & 1;
        float sum = 0.f;
        #pragma unroll
        for (int ww = 0; ww < 8; ww++) sum += redc[ww][bb][comp];
        part[((b0 + bb) * 128 + ht) * 2 + comp] = sum;
    }
}

// ---------------------------------------------------------------------------
// Store wave + loss finalize. Blocks 0..2047: dW tiles. Blocks 2048/2049:
// loss for layer 0/1 (means from prev + partial sums), hidden under the wave.
// ---------------------------------------------------------------------------
__global__ void __launch_bounds__(128)
store_final_kernel(const float* __restrict__ a_all,
                   const float* __restrict__ t_all,
                   float* __restrict__ dW0,
                   float* __restrict__ dW1,
                   const float* __restrict__ part_all,  // (2,32,128,2)
                   const float* __restrict__ ps0,
                   const float* __restrict__ ps1,
                   const int*   __restrict__ bf_ptr,
                   float* __restrict__ losses)
{
    const int bid = blockIdx.x;
    const int tid = threadIdx.x;          // 128

    if (bid >= 2048) {                    // loss finalize for layer l
        const int l = bid - 2048;
        const float* prev = l ? ps1 : ps0;
        const float* part = part_all + l * (BB * 128 * 2);
        __shared__ float meansh[BB];
        __shared__ float vsh[BB];
        const int w = tid >> 5, lane = tid & 31;

        // means: 4 warps, each handles 8 b-rows
        for (int r = 0; r < 8; r++) {
            const int b = w * 8 + r;
            const float* row = prev + (size_t)b * NN;
            float s = 0.f;
            #pragma unroll
            for (int k = 0; k < NN / 32; k++) s += row[lane + 32 * k];
            #pragma unroll
            for (int o = 16; o; o >>= 1) s += __shfl_down_sync(0xffffffffu, s, o);
            if (lane == 0) meansh[b] = s * (1.0f / NN);
        }
        __syncthreads();

        // partial sums: 4 threads per b, each sums 32 htiles
        const int b = tid >> 2, seg = tid & 3;
        float s1 = 0.f, s2 = 0.f;
        for (int h = seg * 32; h < seg * 32 + 32; h++) {
            s1 += part[(b * 128 + h) * 2 + 0];
            s2 += part[(b * 128 + h) * 2 + 1];
        }
        #pragma unroll
        for (int o = 2; o; o >>= 1) {
            s1 += __shfl_down_sync(0xffffffffu, s1, o);
            s2 += __shfl_down_sync(0xffffffffu, s2, o);
        }
        if (seg == 0) vsh[b] = s1 - meansh[b] * s2;
        __syncthreads();
        if (tid == 0) {
            float tot = 0.f;
            #pragma unroll
            for (int i = 0; i < BB; i++) tot += vsh[i];
            losses[l] = -((float)(*bf_ptr)) * tot * (1.0f / (float)BB);
        }
        return;
    }

    __shared__ float as_[32];
    const int layer = bid >> 10;
    const int rem   = bid & 1023;
    const int b     = rem >> 5;
    const int tile  = rem & 31;           // 32-row tile

    const float*  a = a_all + layer * (BB * NN) + b * NN + tile * 32;
    const float2* t = (const float2*)(t_all + layer * (BB * NN) + b * NN);
    if (tid < 32) as_[tid] = a[tid];
    float2 tv[4];
    #pragma unroll
    for (int j = 0; j < 4; j++) tv[j] = t[tid + 128 * j];
    __syncthreads();

    float* dst = (layer ? dW1 : dW0)
               + (size_t)b * NN * NN + (size_t)tile * 32 * NN;
    #pragma unroll 4
    for (int i = 0; i < 32; i++) {
        float av = as_[i];
        float* row = dst + (size_t)i * NN;
        #pragma unroll
        for (int j = 0; j < 4; j++) {
            float2 v;
            v.x = av * tv[j].x;
            v.y = av * tv[j].y;
            __stcs((float2*)row + tid + 128 * j, v);
        }
    }
}

extern "C" void kernel_launch(void* const* d_in, const int* in_sizes, int n_in,
                              void* d_out, int out_size) {
    (void)in_sizes; (void)n_in; (void)out_size;
    const float* inp  = (const float*)d_in[0];
    const float* W0   = (const float*)d_in[1];
    const float* W1   = (const float*)d_in[2];
    const float* mem0 = (const float*)d_in[3];
    const float* mem1 = (const float*)d_in[4];
    const float* ps0  = (const float*)d_in[5];
    const float* ps1  = (const float*)d_in[6];
    const float* it0  = (const float*)d_in[7];
    const float* it1  = (const float*)d_in[8];
    const int*   bf   = (const int*)d_in[9];

    float* out    = (float*)d_out;
    float* spk1_o = out;                               // (32,1024)
    float* mem0_o = out + BB * NN;                     // (32,1024)
    float* mem1_o = out + 2 * BB * NN;                 // (32,1024)
    float* loss_o = out + 3 * BB * NN;                 // (2,)
    float* dW0_o  = out + 3 * BB * NN + 2;             // (32,1024,1024)
    float* dW1_o  = dW0_o + (size_t)BB * NN * NN;      // (32,1024,1024)

    float* spk0_s; cudaGetSymbolAddress((void**)&spk0_s, g_spk0);
    float* a_s;    cudaGetSymbolAddress((void**)&a_s,    g_a);
    float* t_s;    cudaGetSymbolAddress((void**)&t_s,    g_t);
    float* part_s; cudaGetSymbolAddress((void**)&part_s, g_part);

    dim3 cgrid(128, BB / BG);
    compute_kernel<<<cgrid, 256>>>(inp, W0, mem0, ps0, it0, bf,
                                   mem0_o, spk0_s, a_s, t_s, part_s);
    compute_kernel<<<cgrid, 256>>>(spk0_s, W1, mem1, ps1, it1, bf,
                                   mem1_o, spk1_o,
                                   a_s + BB * NN, t_s + BB * NN,
                                   part_s + BB * 128 * 2);

    store_final_kernel<<<2050, 128>>>(a_s, t_s, dW0_o, dW1_o,
                                      part_s, ps0, ps1, bf, loss_o);
}

// round 7
// speedup vs baseline: 2.5665x; 1.0512x over previous
#include <cuda_runtime.h>

#define BETA  0.95f
#define PI_F  3.141592653589793f
#define BB    32
#define NN    1024
#define BG    4

// Scratch (device globals — no allocation allowed)
__device__ float g_spk0[BB * NN];
__device__ float g_a[2 * BB * NN];         // bf * prev * surrogate(mem-1)
__device__ float g_t[2 * BB * NN];         // trace = beta*itr + x
__device__ float g_part[2 * BB * 128 * 2]; // per-(layer,b,htile) {spk*prev, spk}

// ---------------------------------------------------------------------------
// Layer compute (device fn): one warp per h-row, lanes split K, x read
// directly from gmem (L1-broadcast across the block's 8 warps — no smem
// staging, no prologue sync). Block = 8 h-rows x 4 batches, 256 threads.
// cid in [0,1024): ht = cid>>3, b0 = (cid&7)*4.
// ---------------------------------------------------------------------------
__device__ __forceinline__ void layer_compute(
    const float* __restrict__ x,
    const float* __restrict__ W,
    const float* __restrict__ mem_in,
    const float* __restrict__ prev,
    const float* __restrict__ itr,
    const int*   __restrict__ bf_ptr,
    float* __restrict__ mem_out,
    float* __restrict__ spk_out,
    float* __restrict__ a_out,
    float* __restrict__ t_out,
    float* __restrict__ part,
    int cid)
{
    __shared__ float redc[8][BG][2];
    const int tid  = threadIdx.x;
    const int w    = tid >> 5, lane = tid & 31;
    const int ht   = cid >> 3;
    const int b0   = (cid & 7) * BG;

    // trace emit (one htile per bgroup)
    if (ht == 0) {
        #pragma unroll
        for (int r = 0; r < BG; r++) {
            const float* trow = itr + (size_t)(b0 + r) * NN;
            const float* xrow = x   + (size_t)(b0 + r) * NN;
            for (int k = tid; k < NN; k += 256)
                t_out[(size_t)(b0 + r) * NN + k] = BETA * trow[k] + xrow[k];
        }
    }

    const int h = ht * 8 + w;
    const float4* wr  = (const float4*)(W + (size_t)h * NN);
    const float*  xb  = x + (size_t)b0 * NN;
    const float4* x0p = (const float4*)(xb);
    const float4* x1p = (const float4*)(xb + NN);
    const float4* x2p = (const float4*)(xb + 2 * NN);
    const float4* x3p = (const float4*)(xb + 3 * NN);

    float acc0 = 0.f, acc1 = 0.f, acc2 = 0.f, acc3 = 0.f;
    #pragma unroll
    for (int i = 0; i < 8; i++) {
        const int o = i * 32 + lane;
        float4 wv = __ldg(wr + o);
        float4 v;
        v = __ldg(x0p + o);
        acc0 = fmaf(wv.x, v.x, fmaf(wv.y, v.y, fmaf(wv.z, v.z, fmaf(wv.w, v.w, acc0))));
        v = __ldg(x1p + o);
        acc1 = fmaf(wv.x, v.x, fmaf(wv.y, v.y, fmaf(wv.z, v.z, fmaf(wv.w, v.w, acc1))));
        v = __ldg(x2p + o);
        acc2 = fmaf(wv.x, v.x, fmaf(wv.y, v.y, fmaf(wv.z, v.z, fmaf(wv.w, v.w, acc2))));
        v = __ldg(x3p + o);
        acc3 = fmaf(wv.x, v.x, fmaf(wv.y, v.y, fmaf(wv.z, v.z, fmaf(wv.w, v.w, acc3))));
    }
    #pragma unroll
    for (int o = 16; o; o >>= 1) {
        acc0 += __shfl_xor_sync(0xffffffffu, acc0, o);
        acc1 += __shfl_xor_sync(0xffffffffu, acc1, o);
        acc2 += __shfl_xor_sync(0xffffffffu, acc2, o);
        acc3 += __shfl_xor_sync(0xffffffffu, acc3, o);
    }

    if (lane < BG) {
        float dot = (lane == 0) ? acc0 : (lane == 1) ? acc1
                  : (lane == 2) ? acc2 : acc3;
        const int idx = (b0 + lane) * NN + h;
        float m = BETA * mem_in[idx] + dot;
        float s = (m > 1.0f) ? 1.0f : 0.0f;
        m -= s;
        mem_out[idx] = m;
        spk_out[idx] = s;

        float pv  = prev[idx];
        float u   = PI_F * (m - 1.0f);
        float sur = 1.0f / (PI_F * (1.0f + u * u));
        a_out[idx] = ((float)(*bf_ptr)) * pv * sur;

        redc[w][lane][0] = s * pv;
        redc[w][lane][1] = s;
    }
    __syncthreads();
    if (tid < 2 * BG) {
        const int bb = tid >> 1, comp = tid & 1;
        float sum = 0.f;
        #pragma unroll
        for (int ww = 0; ww < 8; ww++) sum += redc[ww][bb][comp];
        part[((b0 + bb) * 128 + ht) * 2 + comp] = sum;
    }
}

// ---------------------------------------------------------------------------
// Store one 64-row x 1024-col dW tile, 256 threads, streaming stores.
// sid in [0,512): b = sid>>4, tile = sid&15.
// ---------------------------------------------------------------------------
__device__ __forceinline__ void store_tile(
    const float* __restrict__ a_base,   // (32,1024) for this layer
    const float* __restrict__ t_base,   // (32,1024)
    float* __restrict__ dW,
    int sid)
{
    __shared__ float as_[64];
    const int tid  = threadIdx.x;
    const int b    = sid >> 4;
    const int tile = sid & 15;

    const float*  a = a_base + b * NN + tile * 64;
    const float2* t = (const float2*)(t_base + b * NN);
    if (tid < 64) as_[tid] = a[tid];
    const float2 t0 = t[tid];
    const float2 t1 = t[tid + 256];
    __syncthreads();

    float* dst = dW + (size_t)b * NN * NN + (size_t)tile * 64 * NN;
    #pragma unroll 4
    for (int i = 0; i < 64; i++) {
        const float av = as_[i];
        float* row = dst + (size_t)i * NN;
        float2 v0, v1;
        v0.x = av * t0.x; v0.y = av * t0.y;
        v1.x = av * t1.x; v1.y = av * t1.y;
        __stcs((float2*)row + tid,       v0);
        __stcs((float2*)row + tid + 256, v1);
    }
}

// ---------------------------------------------------------------------------
// Loss finalize for layer l (256 threads).
// ---------------------------------------------------------------------------
__device__ __forceinline__ void loss_finalize(
    const float* __restrict__ prev,
    const float* __restrict__ part,     // (32,128,2) for this layer
    const int*   __restrict__ bf_ptr,
    float* __restrict__ loss_slot)
{
    __shared__ float meansh[BB];
    __shared__ float vsh[BB];
    const int tid = threadIdx.x;
    const int w = tid >> 5, lane = tid & 31;

    #pragma unroll
    for (int r = 0; r < 4; r++) {        // 8 warps x 4 rows = 32 b
        const int b = w * 4 + r;
        const float* row = prev + (size_t)b * NN;
        float s = 0.f;
        #pragma unroll
        for (int k = 0; k < NN / 32; k++) s += row[lane + 32 * k];
        #pragma unroll
        for (int o = 16; o; o >>= 1) s += __shfl_down_sync(0xffffffffu, s, o);
        if (lane == 0) meansh[b] = s * (1.0f / NN);
    }
    __syncthreads();

    const int b = tid >> 3, seg = tid & 7;   // 8 threads per b
    float s1 = 0.f, s2 = 0.f;
    for (int h = seg * 16; h < seg * 16 + 16; h++) {
        s1 += part[(b * 128 + h) * 2 + 0];
        s2 += part[(b * 128 + h) * 2 + 1];
    }
    #pragma unroll
    for (int o = 4; o; o >>= 1) {
        s1 += __shfl_down_sync(0xffffffffu, s1, o);
        s2 += __shfl_down_sync(0xffffffffu, s2, o);
    }
    if (seg == 0) vsh[b] = s1 - meansh[b] * s2;
    __syncthreads();
    if (tid == 0) {
        float tot = 0.f;
        #pragma unroll
        for (int i = 0; i < BB; i++) tot += vsh[i];
        *loss_slot = -((float)(*bf_ptr)) * tot * (1.0f / (float)BB);
    }
}

// ---------------------------------------------------------------------------
// K1: compute layer 0 (1024 blocks)
// ---------------------------------------------------------------------------
__global__ void __launch_bounds__(256)
k1_compute0(const float* __restrict__ inp, const float* __restrict__ W0,
            const float* __restrict__ mem0, const float* __restrict__ ps0,
            const float* __restrict__ it0, const int* __restrict__ bf,
            float* __restrict__ mem0_o)
{
    layer_compute(inp, W0, mem0, ps0, it0, bf,
                  mem0_o, g_spk0, g_a, g_t, g_part, blockIdx.x);
}

// ---------------------------------------------------------------------------
// K2: compute layer 1 (blocks 0..1023) CONCURRENT with store dW0 (1024..1535)
// ---------------------------------------------------------------------------
__global__ void __launch_bounds__(256)
k2_mid(const float* __restrict__ W1, const float* __restrict__ mem1,
       const float* __restrict__ ps1, const float* __restrict__ it1,
       const int* __restrict__ bf,
       float* __restrict__ mem1_o, float* __restrict__ spk1_o,
       float* __restrict__ dW0)
{
    const int bid = blockIdx.x;
    if (bid < 1024) {
        layer_compute(g_spk0, W1, mem1, ps1, it1, bf,
                      mem1_o, spk1_o,
                      g_a + BB * NN, g_t + BB * NN,
                      g_part + BB * 128 * 2, bid);
    } else {
        store_tile(g_a, g_t, dW0, bid - 1024);
    }
}

// ---------------------------------------------------------------------------
// K3: store dW1 (blocks 0..511) + loss finalize (512, 513)
// ---------------------------------------------------------------------------
__global__ void __launch_bounds__(256)
k3_tail(float* __restrict__ dW1,
        const float* __restrict__ ps0, const float* __restrict__ ps1,
        const int* __restrict__ bf, float* __restrict__ loss_o)
{
    const int bid = blockIdx.x;
    if (bid < 512) {
        store_tile(g_a + BB * NN, g_t + BB * NN, dW1, bid);
    } else {
        const int l = bid - 512;
        loss_finalize(l ? ps1 : ps0,
                      g_part + l * (BB * 128 * 2), bf, loss_o + l);
    }
}

extern "C" void kernel_launch(void* const* d_in, const int* in_sizes, int n_in,
                              void* d_out, int out_size) {
    (void)in_sizes; (void)n_in; (void)out_size;
    const float* inp  = (const float*)d_in[0];
    const float* W0   = (const float*)d_in[1];
    const float* W1   = (const float*)d_in[2];
    const float* mem0 = (const float*)d_in[3];
    const float* mem1 = (const float*)d_in[4];
    const float* ps0  = (const float*)d_in[5];
    const float* ps1  = (const float*)d_in[6];
    const float* it0  = (const float*)d_in[7];
    const float* it1  = (const float*)d_in[8];
    const int*   bf   = (const int*)d_in[9];

    float* out    = (float*)d_out;
    float* spk1_o = out;                               // (32,1024)
    float* mem0_o = out + BB * NN;                     // (32,1024)
    float* mem1_o = out + 2 * BB * NN;                 // (32,1024)
    float* loss_o = out + 3 * BB * NN;                 // (2,)
    float* dW0_o  = out + 3 * BB * NN + 2;             // (32,1024,1024)
    float* dW1_o  = dW0_o + (size_t)BB * NN * NN;      // (32,1024,1024)

    k1_compute0<<<1024, 256>>>(inp, W0, mem0, ps0, it0, bf, mem0_o);
    k2_mid<<<1536, 256>>>(W1, mem1, ps1, it1, bf, mem1_o, spk1_o, dW0_o);
    k3_tail<<<514, 256>>>(dW1_o, ps0, ps1, bf, loss_o);
}

// round 8
// speedup vs baseline: 2.9860x; 1.1635x over previous
#include <cuda_runtime.h>

#define BETA  0.95f
#define PI_F  3.141592653589793f
#define BB    32
#define NN    1024

// Scratch (device globals — no allocation allowed)
__device__ float g_spk0[BB * NN];
__device__ float g_mean[2 * BB];
__device__ float g_part[2 * BB * 128 * 2];   // per-(layer,b,htile) {spk*prev, spk}

// ---------------------------------------------------------------------------
// Fused layer block: GEMM tile (8 h-rows x 4 batches) -> LIF -> immediately
// store its 32 dW rows (128 KB). x and trace staged in smem; W front-batched
// into 8 float4 regs (MLP=8). 256 threads.
// cid in [0,1024): ht = cid>>3, b0 = (cid&7)*4.
// ---------------------------------------------------------------------------
__device__ __forceinline__ void fused_layer(
    const float* __restrict__ x,
    const float* __restrict__ W,
    const float* __restrict__ mem_in,
    const float* __restrict__ prev,
    const float* __restrict__ itr,
    const int*   __restrict__ bf_ptr,
    float* __restrict__ mem_out,
    float* __restrict__ spk_out,
    float* __restrict__ dW,
    float* __restrict__ part,     // (32,128,2) this layer
    int cid)
{
    __shared__ __align__(16) float xs[4][NN];
    __shared__ __align__(16) float ts[4][NN];
    __shared__ float as_[8][4];
    __shared__ float redc[8][4][2];

    const int tid = threadIdx.x;           // 256
    const int w   = tid >> 5, lane = tid & 31;
    const int ht  = cid >> 3;
    const int b0  = (cid & 7) * 4;

    // ---- prologue: stage x and trace = beta*itr + x into smem ----
    {
        const float4* xp = (const float4*)(x   + (size_t)b0 * NN);
        const float4* ip = (const float4*)(itr + (size_t)b0 * NN);
        float4 xv[4], iv[4];
        #pragma unroll
        for (int r = 0; r < 4; r++) {
            xv[r] = __ldg(xp + tid + 256 * r);
            iv[r] = __ldg(ip + tid + 256 * r);
        }
        float4* xsp = (float4*)xs;
        float4* tsp = (float4*)ts;
        #pragma unroll
        for (int r = 0; r < 4; r++) {
            xsp[tid + 256 * r] = xv[r];
            float4 t;
            t.x = fmaf(BETA, iv[r].x, xv[r].x);
            t.y = fmaf(BETA, iv[r].y, xv[r].y);
            t.z = fmaf(BETA, iv[r].z, xv[r].z);
            t.w = fmaf(BETA, iv[r].w, xv[r].w);
            tsp[tid + 256 * r] = t;
        }
    }
    __syncthreads();

    // ---- GEMM: warp w owns h-row, lanes split K; W batched upfront ----
    const int h = ht * 8 + w;
    const float4* wr = (const float4*)(W + (size_t)h * NN);
    float4 wv[8];
    #pragma unroll
    for (int i = 0; i < 8; i++) wv[i] = __ldg(wr + i * 32 + lane);

    const float4* x0p = (const float4*)xs[0];
    const float4* x1p = (const float4*)xs[1];
    const float4* x2p = (const float4*)xs[2];
    const float4* x3p = (const float4*)xs[3];
    float acc0 = 0.f, acc1 = 0.f, acc2 = 0.f, acc3 = 0.f;
    #pragma unroll
    for (int i = 0; i < 8; i++) {
        const int o = i * 32 + lane;
        const float4 wvv = wv[i];
        float4 v;
        v = x0p[o];
        acc0 = fmaf(wvv.x, v.x, fmaf(wvv.y, v.y, fmaf(wvv.z, v.z, fmaf(wvv.w, v.w, acc0))));
        v = x1p[o];
        acc1 = fmaf(wvv.x, v.x, fmaf(wvv.y, v.y, fmaf(wvv.z, v.z, fmaf(wvv.w, v.w, acc1))));
        v = x2p[o];
        acc2 = fmaf(wvv.x, v.x, fmaf(wvv.y, v.y, fmaf(wvv.z, v.z, fmaf(wvv.w, v.w, acc2))));
        v = x3p[o];
        acc3 = fmaf(wvv.x, v.x, fmaf(wvv.y, v.y, fmaf(wvv.z, v.z, fmaf(wvv.w, v.w, acc3))));
    }
    #pragma unroll
    for (int o = 16; o; o >>= 1) {
        acc0 += __shfl_xor_sync(0xffffffffu, acc0, o);
        acc1 += __shfl_xor_sync(0xffffffffu, acc1, o);
        acc2 += __shfl_xor_sync(0xffffffffu, acc2, o);
        acc3 += __shfl_xor_sync(0xffffffffu, acc3, o);
    }

    // ---- LIF epilogue: lanes 0..3 handle batch b0+lane ----
    if (lane < 4) {
        float dot = (lane == 0) ? acc0 : (lane == 1) ? acc1
                  : (lane == 2) ? acc2 : acc3;
        const int idx = (b0 + lane) * NN + h;
        float m = BETA * mem_in[idx] + dot;
        float s = (m > 1.0f) ? 1.0f : 0.0f;
        m -= s;
        mem_out[idx] = m;
        spk_out[idx] = s;

        float pv  = prev[idx];
        float u   = PI_F * (m - 1.0f);
        float sur = 1.0f / (PI_F * (1.0f + u * u));
        as_[w][lane] = ((float)(*bf_ptr)) * pv * sur;

        redc[w][lane][0] = s * pv;
        redc[w][lane][1] = s;
    }
    __syncthreads();

    if (tid < 8) {
        const int bb = tid >> 1, comp = tid & 1;
        float sum = 0.f;
        #pragma unroll
        for (int ww = 0; ww < 8; ww++) sum += redc[ww][bb][comp];
        part[((b0 + bb) * 128 + ht) * 2 + comp] = sum;
    }

    // ---- store phase: 32 dW rows, thread owns cols (2t,2t+1)+(512+2t,..) ----
    float2 tA[4], tB[4];
    #pragma unroll
    for (int bb = 0; bb < 4; bb++) {
        tA[bb] = *((const float2*)ts[bb] + tid);
        tB[bb] = *((const float2*)ts[bb] + tid + 256);
    }

    #pragma unroll
    for (int bb = 0; bb < 4; bb++) {
        float* brow = dW + (size_t)(b0 + bb) * NN * NN + (size_t)(ht * 8) * NN;
        #pragma unroll
        for (int w2 = 0; w2 < 8; w2++) {
            const float av = as_[w2][bb];
            float* row = brow + (size_t)w2 * NN;
            float2 v0, v1;
            v0.x = av * tA[bb].x; v0.y = av * tA[bb].y;
            v1.x = av * tB[bb].x; v1.y = av * tB[bb].y;
            __stcs((float2*)row + tid,       v0);
            __stcs((float2*)row + tid + 256, v1);
        }
    }
}

// ---------------------------------------------------------------------------
// Mean of a (32,1024) matrix's rows -> g_mean[l*32 + b] (one block, 256 thr)
// ---------------------------------------------------------------------------
__device__ __forceinline__ void row_means(const float* __restrict__ prev, int l)
{
    const int tid = threadIdx.x;
    const int w = tid >> 5, lane = tid & 31;
    #pragma unroll
    for (int r = 0; r < 4; r++) {          // 8 warps x 4 rows
        const int b = w * 4 + r;
        const float* row = prev + (size_t)b * NN;
        float s = 0.f;
        #pragma unroll
        for (int k = 0; k < NN / 32; k++) s += row[lane + 32 * k];
        #pragma unroll
        for (int o = 16; o; o >>= 1) s += __shfl_down_sync(0xffffffffu, s, o);
        if (lane == 0) g_mean[l * BB + b] = s * (1.0f / NN);
    }
}

// ---------------------------------------------------------------------------
// K1: fused layer 0 (1024 blocks) + means of ps0/ps1 (blocks 1024,1025)
// ---------------------------------------------------------------------------
__global__ void __launch_bounds__(256)
k1_layer0(const float* __restrict__ inp, const float* __restrict__ W0,
          const float* __restrict__ mem0, const float* __restrict__ ps0,
          const float* __restrict__ ps1, const float* __restrict__ it0,
          const int* __restrict__ bf,
          float* __restrict__ mem0_o, float* __restrict__ dW0)
{
    const int bid = blockIdx.x;
    if (bid < 1024) {
        fused_layer(inp, W0, mem0, ps0, it0, bf,
                    mem0_o, g_spk0, dW0, g_part, bid);
    } else {
        row_means(bid == 1024 ? ps0 : ps1, bid - 1024);
    }
}

// ---------------------------------------------------------------------------
// K2: fused layer 1 (1024 blocks)
// ---------------------------------------------------------------------------
__global__ void __launch_bounds__(256)
k2_layer1(const float* __restrict__ W1, const float* __restrict__ mem1,
          const float* __restrict__ ps1, const float* __restrict__ it1,
          const int* __restrict__ bf,
          float* __restrict__ mem1_o, float* __restrict__ spk1_o,
          float* __restrict__ dW1)
{
    fused_layer(g_spk0, W1, mem1, ps1, it1, bf,
                mem1_o, spk1_o, dW1, g_part + BB * 128 * 2, blockIdx.x);
}

// ---------------------------------------------------------------------------
// K3: loss finalize, 1 block 256 threads.
// ---------------------------------------------------------------------------
__global__ void __launch_bounds__(256)
k3_loss(const int* __restrict__ bf, float* __restrict__ loss_o)
{
    __shared__ float vsh[64];
    const int tid  = threadIdx.x;
    const int pair = tid >> 2;            // 0..63 = (l,b)
    const int seg  = tid & 3;
    const int l = pair >> 5, b = pair & 31;
    const float* part = g_part + l * (BB * 128 * 2) + b * 128 * 2;
    float s1 = 0.f, s2 = 0.f;
    for (int h2 = seg * 32; h2 < seg * 32 + 32; h2++) {
        s1 += part[h2 * 2 + 0];
        s2 += part[h2 * 2 + 1];
    }
    #pragma unroll
    for (int o = 2; o; o >>= 1) {
        s1 += __shfl_down_sync(0xffffffffu, s1, o);
        s2 += __shfl_down_sync(0xffffffffu, s2, o);
    }
    if (seg == 0) vsh[pair] = s1 - g_mean[l * BB + b] * s2;
    __syncthreads();
    if (tid < 2) {
        float tot = 0.f;
        #pragma unroll
        for (int i = 0; i < BB; i++) tot += vsh[tid * BB + i];
        loss_o[tid] = -((float)(*bf)) * tot * (1.0f / (float)BB);
    }
}

extern "C" void kernel_launch(void* const* d_in, const int* in_sizes, int n_in,
                              void* d_out, int out_size) {
    (void)in_sizes; (void)n_in; (void)out_size;
    const float* inp  = (const float*)d_in[0];
    const float* W0   = (const float*)d_in[1];
    const float* W1   = (const float*)d_in[2];
    const float* mem0 = (const float*)d_in[3];
    const float* mem1 = (const float*)d_in[4];
    const float* ps0  = (const float*)d_in[5];
    const float* ps1  = (const float*)d_in[6];
    const float* it0  = (const float*)d_in[7];
    const float* it1  = (const float*)d_in[8];
    const int*   bf   = (const int*)d_in[9];

    float* out    = (float*)d_out;
    float* spk1_o = out;                               // (32,1024)
    float* mem0_o = out + BB * NN;                     // (32,1024)
    float* mem1_o = out + 2 * BB * NN;                 // (32,1024)
    float* loss_o = out + 3 * BB * NN;                 // (2,)
    float* dW0_o  = out + 3 * BB * NN + 2;             // (32,1024,1024)
    float* dW1_o  = dW0_o + (size_t)BB * NN * NN;      // (32,1024,1024)

    k1_layer0<<<1026, 256>>>(inp, W0, mem0, ps0, ps1, it0, bf, mem0_o, dW0_o);
    k2_layer1<<<1024, 256>>>(W1, mem1, ps1, it1, bf, mem1_o, spk1_o, dW1_o);
    k3_loss<<<1, 256>>>(bf, loss_o);
}